// round 8
// baseline (speedup 1.0000x reference)
#include <cuda_runtime.h>

// Problem constants (match reference)
#define BATCH    2
#define NIMG     2
#define VOL      (96*96*96)          // 884736, divisible by 4
#define V4       (VOL/4)             // 221184
#define EPSF     1e-8f

// Hypothesis R8: XLA rewrote the bin_pos division as multiply-by-reciprocal:
//   pos = fl32( num * fl32(1 / bws) )   (both IEEE round-to-nearest)
// The floor(pos) decision sits ~1 ulp from an integer at every voxel, so we
// must replicate this exact two-rounding sequence.
__device__ __forceinline__ float recip_mul(float num, float rcp) {
    return __fmul_rn(num, rcp);
}

__device__ __forceinline__ float div_approx(float a, float b) {
    float r;
    asm("div.approx.f32 %0, %1, %2;" : "=f"(r) : "f"(a), "f"(b));
    return r;
}

// cubic B-spline Parzen window, sigma = 1 (continuous -> rounding-insensitive)
__device__ __forceinline__ float bspline(float d) {
    float ad  = fabsf(d);
    float ad2 = ad * ad;
    float w_in  = (3.0f * ad2 * ad - 6.0f * ad2 + 4.0f) * (1.0f / 6.0f);
    float t     = 2.0f - ad;
    float w_out = t * t * t * (1.0f / 6.0f);
    return ad < 1.0f ? w_in : (ad < 2.0f ? w_out : 0.0f);
}

__global__ void __launch_bounds__(256)
parzen_density_kernel(const float* __restrict__ img,
                      const float* __restrict__ mask,
                      float* __restrict__ out)
{
    int t = blockIdx.x * blockDim.x + threadIdx.x;
    if (t >= BATCH * V4) return;

    int b  = t / V4;
    int v4 = t - b * V4;
    long base = (long)b * NIMG * VOL + (long)v4 * 4;

    float4 x0v = *(const float4*)(img  + base);
    float4 x1v = *(const float4*)(img  + base + VOL);
    float4 m0v = *(const float4*)(mask + base);
    float4 m1v = *(const float4*)(mask + base + VOL);

    float xa[4] = {x0v.x, x0v.y, x0v.z, x0v.w};
    float xb[4] = {x1v.x, x1v.y, x1v.z, x1v.w};
    float ma[4] = {m0v.x, m0v.y, m0v.z, m0v.w};
    float mb[4] = {m1v.x, m1v.y, m1v.z, m1v.w};
    float oa[4], ob[4];

#pragma unroll
    for (int l = 0; l < 4; l++) {
        float a = xa[l], c = xb[l];
        float mx = fmaxf(a, c);
        float mn = fminf(a, c);
        // critical chain: pin exact IEEE op sequence (matches reference f32 ops)
        float D    = __fsub_rn(mx, mn);
        float bw   = __fmul_rn(D, 0.0625f);               // (max-min)/16, exact scale
        float pmin = __fsub_rn(mn, __fmul_rn(bw, 2.0f));  // pad_min, one rounding
        float bws  = fmaxf(bw, EPSF);                     // clip(bin_width, EPS)

        float num0 = __fsub_rn(a, pmin);                  // f32 numerators (as ref)
        float num1 = __fsub_rn(c, pmin);

        // IEEE reciprocal once, then IEEE multiply (hypothesized XLA rewrite)
        float rcp  = __frcp_rn(bws);
        float pos0 = recip_mul(num0, rcp);
        float pos1 = recip_mul(num1, rcp);

        float f0 = floorf(pos0);
        float f1 = floorf(pos1);

        // bin_idx clipped to [RADIUS, RADIUS+NUM_BINS-1] = [2,17]
        float bi0 = fminf(fmaxf(f0, 2.0f), 17.0f);
        float bi1 = fminf(fmaxf(f1, 2.0f), 17.0f);

        // histogram denominator = sum of all 8 scattered window weights
        float s = 0.0f;
#pragma unroll
        for (int r = 0; r < 4; r++) {
            float kk0 = bi0 - 1.0f + (float)r;
            float kk1 = bi1 - 1.0f + (float)r;
            s += bspline(pos0 - kk0);
            s += bspline(pos1 - kk1);
        }
        float denom = fmaxf(s, EPSF);

        // per-image gather bin: clip(floor, 0, K-1=19)
        int i0 = (int)bi0, i1 = (int)bi1;
        int g0 = (int)fminf(fmaxf(f0, 0.0f), 19.0f);
        int g1 = (int)fminf(fmaxf(f1, 0.0f), 19.0f);

        // hist value at gathered bin = contributions from each window covering it
        float h0 = 0.0f, h1 = 0.0f;
        if (g0 >= i0 - 1 && g0 <= i0 + 2) h0 += bspline(pos0 - (float)g0);
        if (g0 >= i1 - 1 && g0 <= i1 + 2) h0 += bspline(pos1 - (float)g0);
        if (g1 >= i0 - 1 && g1 <= i0 + 2) h1 += bspline(pos0 - (float)g1);
        if (g1 >= i1 - 1 && g1 <= i1 + 2) h1 += bspline(pos1 - (float)g1);

        float d0 = div_approx(h0, denom);   // continuous (rounding-insensitive)
        float d1 = div_approx(h1, denom);

        oa[l] = (ma[l] != 0.0f) ? d0 : 0.0f;
        ob[l] = (mb[l] != 0.0f) ? d1 : 0.0f;
    }

    *(float4*)(out + base)       = make_float4(oa[0], oa[1], oa[2], oa[3]);
    *(float4*)(out + base + VOL) = make_float4(ob[0], ob[1], ob[2], ob[3]);
}

extern "C" void kernel_launch(void* const* d_in, const int* in_sizes, int n_in,
                              void* d_out, int out_size)
{
    const float* img  = (const float*)d_in[0];   // [2,2,1,96,96,96] f32
    const float* mask = (const float*)d_in[1];   // [2,2,96,96,96]   f32
    float* out = (float*)d_out;                  // [2,2,96,96,96]   f32

    int total  = BATCH * V4;                     // 442368 threads
    int block  = 256;
    int grid   = (total + block - 1) / block;    // 1728 blocks
    parzen_density_kernel<<<grid, block>>>(img, mask, out);
}

// round 9
// speedup vs baseline: 1.7180x; 1.7180x over previous
#include <cuda_runtime.h>

// Problem constants (match reference)
#define NIMG     2
#define VOL      (96*96*96)          // 884736, divisible by 4
#define V4       (VOL/4)             // 221184 = 864 blocks * 256 threads
#define EPSF     1e-8f

// cubic B-spline Parzen window, sigma = 1 (continuous value -> 1-ulp insensitive)
__device__ __forceinline__ float bspline(float d) {
    float ad  = fabsf(d);
    float ad2 = ad * ad;
    float w_in  = (3.0f * ad2 * ad - 6.0f * ad2 + 4.0f) * (1.0f / 6.0f);
    float u     = 2.0f - ad;
    float w_out = u * u * u * (1.0f / 6.0f);
    return ad < 1.0f ? w_in : (ad < 2.0f ? w_out : 0.0f);
}

__global__ void __launch_bounds__(256)
parzen_density_kernel(const float* __restrict__ img,
                      const float* __restrict__ mask,
                      float* __restrict__ out)
{
    int v4  = blockIdx.x * 256 + threadIdx.x;     // [0, V4)
    int b   = blockIdx.y;                         // batch
    int base = b * (NIMG * VOL) + v4 * 4;

    float4 x0v = *(const float4*)(img  + base);
    float4 x1v = *(const float4*)(img  + base + VOL);
    float4 m0v = *(const float4*)(mask + base);
    float4 m1v = *(const float4*)(mask + base + VOL);

    float xa[4] = {x0v.x, x0v.y, x0v.z, x0v.w};
    float xb[4] = {x1v.x, x1v.y, x1v.z, x1v.w};
    float ma[4] = {m0v.x, m0v.y, m0v.z, m0v.w};
    float mb[4] = {m1v.x, m1v.y, m1v.z, m1v.w};
    float oa[4], ob[4];

#pragma unroll
    for (int l = 0; l < 4; l++) {
        float a = xa[l], c = xb[l];
        float mn = fminf(a, c), mx = fmaxf(a, c);
        // critical chain: exact IEEE op sequence matching the reference
        float bw   = __fmul_rn(__fsub_rn(mx, mn), 0.0625f);   // (max-min)/16
        float pmin = __fsub_rn(mn, __fmul_rn(bw, 2.0f));      // pad_min
        float bws  = fmaxf(bw, EPSF);                         // clip(bin_width, EPS)

        // reference divide = rcp.rn + mul.rn (verified R8)
        float rcp  = __frcp_rn(bws);
        float pos0 = __fmul_rn(__fsub_rn(a, pmin), rcp);
        float pos1 = __fmul_rn(__fsub_rn(c, pmin), rcp);

        float f0 = floorf(pos0), f1 = floorf(pos1);
        float bi0 = fminf(fmaxf(f0, 2.0f), 17.0f);            // scatter window center
        float bi1 = fminf(fmaxf(f1, 2.0f), 17.0f);
        int   i0 = (int)bi0,  i1 = (int)bi1;
        int   g0 = (int)fminf(fmaxf(f0, 0.0f), 19.0f);        // gather bin
        int   g1 = (int)fminf(fmaxf(f1, 0.0f), 19.0f);

        float t0 = pos0 - bi0, t1 = pos1 - bi1;
        float h0, h1, dinv;

        if (fminf(t0, t1) >= -0.01f && fmaxf(t0, t1) <= 1.01f) {
            // FAST PATH (≈100% of voxels): each window is the natural 4-tap
            // partition of unity (clip margin ≤0.01 -> dropped tap ≤ 1.7e-7),
            // so denominator = 2 to within 2e-7 of the reference's f32 sum.
            // The gather bin is always inside its own window here.
            h0 = bspline(__fsub_rn(pos0, (float)g0));
            h1 = bspline(__fsub_rn(pos1, (float)g1));
            // cross-window overlap (windows 16 bins apart normally -> never)
            if (g0 >= i1 - 1 && g0 <= i1 + 2) h0 += bspline(pos1 - (float)g0);
            if (g1 >= i0 - 1 && g1 <= i0 + 2) h1 += bspline(pos0 - (float)g1);
            dinv = 0.5f;
        } else {
            // SLOW PATH (degenerate tiny-range voxels): full reference math
            float s = 0.0f;
#pragma unroll
            for (int r = 0; r < 4; r++) {
                s += bspline(pos0 - (bi0 - 1.0f + (float)r));
                s += bspline(pos1 - (bi1 - 1.0f + (float)r));
            }
            h0 = 0.0f; h1 = 0.0f;
            if (g0 >= i0 - 1 && g0 <= i0 + 2) h0 += bspline(pos0 - (float)g0);
            if (g0 >= i1 - 1 && g0 <= i1 + 2) h0 += bspline(pos1 - (float)g0);
            if (g1 >= i0 - 1 && g1 <= i0 + 2) h1 += bspline(pos0 - (float)g1);
            if (g1 >= i1 - 1 && g1 <= i1 + 2) h1 += bspline(pos1 - (float)g1);
            dinv = 1.0f / fmaxf(s, EPSF);     // continuous
        }

        oa[l] = (ma[l] != 0.0f) ? h0 * dinv : 0.0f;
        ob[l] = (mb[l] != 0.0f) ? h1 * dinv : 0.0f;
    }

    *(float4*)(out + base)       = make_float4(oa[0], oa[1], oa[2], oa[3]);
    *(float4*)(out + base + VOL) = make_float4(ob[0], ob[1], ob[2], ob[3]);
}

extern "C" void kernel_launch(void* const* d_in, const int* in_sizes, int n_in,
                              void* d_out, int out_size)
{
    const float* img  = (const float*)d_in[0];   // [2,2,1,96,96,96] f32
    const float* mask = (const float*)d_in[1];   // [2,2,96,96,96]   f32
    float* out = (float*)d_out;                  // [2,2,96,96,96]   f32

    dim3 grid(V4 / 256, 2);                      // 864 x 2 blocks, exact cover
    parzen_density_kernel<<<grid, 256>>>(img, mask, out);
}

// round 13
// speedup vs baseline: 2.1183x; 1.2330x over previous
#include <cuda_runtime.h>

// Problem constants (match reference)
#define NIMG     2
#define VOL      (96*96*96)          // 884736, divisible by 4
#define V4       (VOL/4)             // 221184 = 864 blocks * 256 threads
#define EPSF     1e-8f

// full cubic B-spline (slow path only)
__device__ __forceinline__ float bspline(float d) {
    float ad  = fabsf(d);
    float ad2 = ad * ad;
    float w_in  = (3.0f * ad2 * ad - 6.0f * ad2 + 4.0f) * (1.0f / 6.0f);
    float u     = 2.0f - ad;
    float w_out = u * u * u * (1.0f / 6.0f);
    return ad < 1.0f ? w_in : (ad < 2.0f ? w_out : 0.0f);
}

__global__ void __launch_bounds__(256)
parzen_density_kernel(const float* __restrict__ img,
                      const float* __restrict__ mask,
                      float* __restrict__ out)
{
    int v4  = blockIdx.x * 256 + threadIdx.x;     // [0, V4)
    int b   = blockIdx.y;                         // batch
    int base = b * (NIMG * VOL) + v4 * 4;

    float4 x0v = *(const float4*)(img  + base);
    float4 x1v = *(const float4*)(img  + base + VOL);
    float4 m0v = *(const float4*)(mask + base);
    float4 m1v = *(const float4*)(mask + base + VOL);

    float xa[4] = {x0v.x, x0v.y, x0v.z, x0v.w};
    float xb[4] = {x1v.x, x1v.y, x1v.z, x1v.w};
    float ma[4] = {m0v.x, m0v.y, m0v.z, m0v.w};
    float mb[4] = {m1v.x, m1v.y, m1v.z, m1v.w};
    float oa[4], ob[4];

#pragma unroll
    for (int l = 0; l < 4; l++) {
        float a = xa[l], c = xb[l];
        float mn = fminf(a, c), mx = fmaxf(a, c);
        // critical chain: exact IEEE op sequence matching the reference
        float bw   = __fmul_rn(__fsub_rn(mx, mn), 0.0625f);   // (max-min)/16
        float pmin = __fsub_rn(mn, __fmul_rn(bw, 2.0f));      // pad_min
        float bws  = fmaxf(bw, EPSF);                         // clip(bin_width, EPS)
        // reference divide = rcp.rn + mul.rn (verified R8)
        float rcp  = __frcp_rn(bws);
        float pos0 = __fmul_rn(__fsub_rn(a, pmin), rcp);
        float pos1 = __fmul_rn(__fsub_rn(c, pmin), rcp);

        float lo = fminf(pos0, pos1), hi = fmaxf(pos0, pos1);
        float r0, r1;

        if (lo >= 1.99f && hi <= 18.01f) {
            // FAST PATH (~100% of voxels). Guard is equivalent to the old
            // t-in-[-0.01,1.01] test. Within it:
            //  - floor(pos) in [1,18] -> gather clip is identity, d = frac(pos)
            //  - d in [0,1) -> inner B-spline branch only
            //  - pos1-pos0 >= 15.9 -> windows disjoint (no cross terms)
            //  - denominator = 2 (partition of unity, error <= 4e-7)
            // half-density = w_inner(d)/2 = d^2*(0.25d - 0.5) + 1/3
            float t0 = __fsub_rn(pos0, floorf(pos0));
            float t1 = __fsub_rn(pos1, floorf(pos1));
            float q0 = t0 * t0, q1 = t1 * t1;
            r0 = fmaf(q0, fmaf(0.25f, t0, -0.5f), 1.0f / 3.0f);
            r1 = fmaf(q1, fmaf(0.25f, t1, -0.5f), 1.0f / 3.0f);
        } else {
            // SLOW PATH (degenerate tiny-range voxels): full reference math
            float f0 = floorf(pos0), f1 = floorf(pos1);
            float bi0 = fminf(fmaxf(f0, 2.0f), 17.0f);
            float bi1 = fminf(fmaxf(f1, 2.0f), 17.0f);
            int   i0 = (int)bi0,  i1 = (int)bi1;
            int   g0 = (int)fminf(fmaxf(f0, 0.0f), 19.0f);
            int   g1 = (int)fminf(fmaxf(f1, 0.0f), 19.0f);
            float s = 0.0f;
#pragma unroll
            for (int r = 0; r < 4; r++) {
                s += bspline(pos0 - (bi0 - 1.0f + (float)r));
                s += bspline(pos1 - (bi1 - 1.0f + (float)r));
            }
            float h0 = 0.0f, h1 = 0.0f;
            if (g0 >= i0 - 1 && g0 <= i0 + 2) h0 += bspline(pos0 - (float)g0);
            if (g0 >= i1 - 1 && g0 <= i1 + 2) h0 += bspline(pos1 - (float)g0);
            if (g1 >= i0 - 1 && g1 <= i0 + 2) h1 += bspline(pos0 - (float)g1);
            if (g1 >= i1 - 1 && g1 <= i1 + 2) h1 += bspline(pos1 - (float)g1);
            float dinv = 1.0f / fmaxf(s, EPSF);
            r0 = h0 * dinv;
            r1 = h1 * dinv;
        }

        oa[l] = (ma[l] != 0.0f) ? r0 : 0.0f;
        ob[l] = (mb[l] != 0.0f) ? r1 : 0.0f;
    }

    *(float4*)(out + base)       = make_float4(oa[0], oa[1], oa[2], oa[3]);
    *(float4*)(out + base + VOL) = make_float4(ob[0], ob[1], ob[2], ob[3]);
}

extern "C" void kernel_launch(void* const* d_in, const int* in_sizes, int n_in,
                              void* d_out, int out_size)
{
    const float* img  = (const float*)d_in[0];   // [2,2,1,96,96,96] f32
    const float* mask = (const float*)d_in[1];   // [2,2,96,96,96]   f32
    float* out = (float*)d_out;                  // [2,2,96,96,96]   f32

    dim3 grid(V4 / 256, 2);                      // 864 x 2 blocks, exact cover
    parzen_density_kernel<<<grid, 256>>>(img, mask, out);
}

// round 14
// speedup vs baseline: 2.1569x; 1.0182x over previous
#include <cuda_runtime.h>

// Problem constants (match reference)
#define NIMG     2
#define VOL      (96*96*96)          // 884736, divisible by 8
#define V8       (VOL/8)             // 110592 = 432 blocks * 256 threads
#define EPSF     1e-8f

// full cubic B-spline (slow path only)
__device__ __forceinline__ float bspline(float d) {
    float ad  = fabsf(d);
    float ad2 = ad * ad;
    float w_in  = (3.0f * ad2 * ad - 6.0f * ad2 + 4.0f) * (1.0f / 6.0f);
    float u     = 2.0f - ad;
    float w_out = u * u * u * (1.0f / 6.0f);
    return ad < 1.0f ? w_in : (ad < 2.0f ? w_out : 0.0f);
}

// per-voxel density pair: bit-exact critical chain + fast/slow path (R13-verified)
__device__ __forceinline__ void density_pair(float a, float c, float& r0, float& r1) {
    float mn = fminf(a, c), mx = fmaxf(a, c);
    float bw   = __fmul_rn(__fsub_rn(mx, mn), 0.0625f);   // (max-min)/16
    float pmin = __fsub_rn(mn, __fmul_rn(bw, 2.0f));      // pad_min
    float bws  = fmaxf(bw, EPSF);                         // clip(bin_width, EPS)
    float rcp  = __frcp_rn(bws);                          // reference divide = rcp.rn+mul.rn
    float pos0 = __fmul_rn(__fsub_rn(a, pmin), rcp);
    float pos1 = __fmul_rn(__fsub_rn(c, pmin), rcp);

    float lo = fminf(pos0, pos1), hi = fmaxf(pos0, pos1);

    if (lo >= 1.99f && hi <= 18.01f) {
        // FAST PATH: gather clip identity, d=frac in [0,1), windows disjoint,
        // denominator = 2 (partition of unity). half-density = t^2(0.25t-0.5)+1/3
        float t0 = __fsub_rn(pos0, floorf(pos0));
        float t1 = __fsub_rn(pos1, floorf(pos1));
        r0 = fmaf(t0 * t0, fmaf(0.25f, t0, -0.5f), 1.0f / 3.0f);
        r1 = fmaf(t1 * t1, fmaf(0.25f, t1, -0.5f), 1.0f / 3.0f);
    } else {
        // SLOW PATH (degenerate tiny-range voxels): full reference math
        float f0 = floorf(pos0), f1 = floorf(pos1);
        float bi0 = fminf(fmaxf(f0, 2.0f), 17.0f);
        float bi1 = fminf(fmaxf(f1, 2.0f), 17.0f);
        int   i0 = (int)bi0,  i1 = (int)bi1;
        int   g0 = (int)fminf(fmaxf(f0, 0.0f), 19.0f);
        int   g1 = (int)fminf(fmaxf(f1, 0.0f), 19.0f);
        float s = 0.0f;
#pragma unroll
        for (int r = 0; r < 4; r++) {
            s += bspline(pos0 - (bi0 - 1.0f + (float)r));
            s += bspline(pos1 - (bi1 - 1.0f + (float)r));
        }
        float h0 = 0.0f, h1 = 0.0f;
        if (g0 >= i0 - 1 && g0 <= i0 + 2) h0 += bspline(pos0 - (float)g0);
        if (g0 >= i1 - 1 && g0 <= i1 + 2) h0 += bspline(pos1 - (float)g0);
        if (g1 >= i0 - 1 && g1 <= i0 + 2) h1 += bspline(pos0 - (float)g1);
        if (g1 >= i1 - 1 && g1 <= i1 + 2) h1 += bspline(pos1 - (float)g1);
        float dinv = 1.0f / fmaxf(s, EPSF);
        r0 = h0 * dinv;
        r1 = h1 * dinv;
    }
}

__global__ void __launch_bounds__(256)
parzen_density_kernel(const float* __restrict__ img,
                      const float* __restrict__ mask,
                      float* __restrict__ out)
{
    int v8  = blockIdx.x * 256 + threadIdx.x;     // [0, V8)
    int b   = blockIdx.y;                         // batch
    int base = b * (NIMG * VOL) + v8 * 8;

    // 12 front-batched 16B loads -> high MLP, single wave (864 blocks total)
    float4 x0a = *(const float4*)(img  + base);
    float4 x0b = *(const float4*)(img  + base + 4);
    float4 x1a = *(const float4*)(img  + base + VOL);
    float4 x1b = *(const float4*)(img  + base + VOL + 4);
    float4 m0a = *(const float4*)(mask + base);
    float4 m0b = *(const float4*)(mask + base + 4);
    float4 m1a = *(const float4*)(mask + base + VOL);
    float4 m1b = *(const float4*)(mask + base + VOL + 4);

    float xa[8] = {x0a.x, x0a.y, x0a.z, x0a.w, x0b.x, x0b.y, x0b.z, x0b.w};
    float xb[8] = {x1a.x, x1a.y, x1a.z, x1a.w, x1b.x, x1b.y, x1b.z, x1b.w};
    float ma[8] = {m0a.x, m0a.y, m0a.z, m0a.w, m0b.x, m0b.y, m0b.z, m0b.w};
    float mb[8] = {m1a.x, m1a.y, m1a.z, m1a.w, m1b.x, m1b.y, m1b.z, m1b.w};
    float oa[8], ob[8];

#pragma unroll
    for (int l = 0; l < 8; l++) {
        float r0, r1;
        density_pair(xa[l], xb[l], r0, r1);
        oa[l] = (ma[l] != 0.0f) ? r0 : 0.0f;
        ob[l] = (mb[l] != 0.0f) ? r1 : 0.0f;
    }

    *(float4*)(out + base)           = make_float4(oa[0], oa[1], oa[2], oa[3]);
    *(float4*)(out + base + 4)       = make_float4(oa[4], oa[5], oa[6], oa[7]);
    *(float4*)(out + base + VOL)     = make_float4(ob[0], ob[1], ob[2], ob[3]);
    *(float4*)(out + base + VOL + 4) = make_float4(ob[4], ob[5], ob[6], ob[7]);
}

extern "C" void kernel_launch(void* const* d_in, const int* in_sizes, int n_in,
                              void* d_out, int out_size)
{
    const float* img  = (const float*)d_in[0];   // [2,2,1,96,96,96] f32
    const float* mask = (const float*)d_in[1];   // [2,2,96,96,96]   f32
    float* out = (float*)d_out;                  // [2,2,96,96,96]   f32

    dim3 grid(V8 / 256, 2);                      // 432 x 2 = 864 blocks, one wave
    parzen_density_kernel<<<grid, 256>>>(img, mask, out);
}